// round 5
// baseline (speedup 1.0000x reference)
#include <cuda_runtime.h>

// AdAP_PZ: nat_loss (pairwise squared-hinge AUC surrogate with moving averages)
//          + LAMBDA * adv KL-style loss.
//
// Key identity: y_pred in [0,1) => MARGIN - (f_i - f_j) > 0 always, so
//   sur[i,j] = (1 - f_i + f_j)^2  with no clipping, and row sums collapse:
//   Sum_j sur[i,j]         = N*c^2     + 2c*S1  + S2      (c = 1 - f_i)
//   Sum_j sur[i,j]*posf[j] = n_pos*c^2 + 2c*S1p + S2p
// Total work becomes O(N) instead of O(N^2).

#define EPSF 1e-12f

constexpr int NPART = 48;   // 48 * 256 = 12288 = N exactly
constexpr int T1 = 256;
constexpr int T2 = 1024;

__device__ double g_s1[NPART];
__device__ double g_s2[NPART];
__device__ double g_s1p[NPART];
__device__ double g_s2p[NPART];
__device__ double g_adv[NPART];
__device__ double g_np[NPART];

__device__ __forceinline__ float xlogy_f(float x) {
    return (x > 0.0f) ? x * __logf(x) : 0.0f;
}

template <int T>
__device__ __forceinline__ double blk_reduce(double v, double* sh, int tid) {
    sh[tid] = v;
    __syncthreads();
#pragma unroll
    for (int s = T / 2; s > 0; s >>= 1) {
        if (tid < s) sh[tid] += sh[tid + s];
        __syncthreads();
    }
    double r = sh[0];
    __syncthreads();
    return r;
}

// Pass 1: per-block partial sums of S1, S2, S1p, S2p, n_pos, and the adv loss.
__global__ void __launch_bounds__(T1) k_partials(const float* __restrict__ yp,
                                                 const float* __restrict__ ypa,
                                                 const int* __restrict__ yt,
                                                 int n) {
    __shared__ double sh[T1];
    int tid = threadIdx.x;
    double s1 = 0, s2 = 0, s1p = 0, s2p = 0, adv = 0, np = 0;
    for (int i = blockIdx.x * T1 + tid; i < n; i += gridDim.x * T1) {
        float f = yp[i];
        float a = ypa[i];
        int pos = (yt[i] == 1);
        double ff = (double)f * (double)f;
        s1 += (double)f;
        s2 += ff;
        if (pos) { s1p += (double)f; s2p += ff; np += 1.0; }
        float t = xlogy_f(f) + xlogy_f(1.0f - f)
                - f * __logf(a + EPSF)
                - (1.0f - f) * __logf(1.0f - a + EPSF);
        adv += (double)t;
    }
    s1  = blk_reduce<T1>(s1, sh, tid);
    s2  = blk_reduce<T1>(s2, sh, tid);
    s1p = blk_reduce<T1>(s1p, sh, tid);
    s2p = blk_reduce<T1>(s2p, sh, tid);
    adv = blk_reduce<T1>(adv, sh, tid);
    np  = blk_reduce<T1>(np, sh, tid);
    if (tid == 0) {
        g_s1[blockIdx.x]  = s1;
        g_s2[blockIdx.x]  = s2;
        g_s1p[blockIdx.x] = s1p;
        g_s2p[blockIdx.x] = s2p;
        g_adv[blockIdx.x] = adv;
        g_np[blockIdx.x]  = np;
    }
}

// Pass 2 (single block): reduce partials, compute per-row nat contributions
// via the closed-form row sums, combine, write scalar.
__global__ void __launch_bounds__(T2) k_final(const float* __restrict__ yp,
                                              const float* __restrict__ u_all,
                                              const float* __restrict__ u_pos,
                                              const int* __restrict__ yt,
                                              const int* __restrict__ idx,
                                              float* __restrict__ out,
                                              int n) {
    __shared__ double sh[T2];
    int tid = threadIdx.x;
    double v;
    v = (tid < NPART) ? g_s1[tid]  : 0.0; double S1  = blk_reduce<T2>(v, sh, tid);
    v = (tid < NPART) ? g_s2[tid]  : 0.0; double S2  = blk_reduce<T2>(v, sh, tid);
    v = (tid < NPART) ? g_s1p[tid] : 0.0; double S1p = blk_reduce<T2>(v, sh, tid);
    v = (tid < NPART) ? g_s2p[tid] : 0.0; double S2p = blk_reduce<T2>(v, sh, tid);
    v = (tid < NPART) ? g_adv[tid] : 0.0; double ADV = blk_reduce<T2>(v, sh, tid);
    v = (tid < NPART) ? g_np[tid]  : 0.0; double NP  = blk_reduce<T2>(v, sh, tid);

    float s1 = (float)S1, s2 = (float)S2, s1p = (float)S1p, s2p = (float)S2p;
    float npf = (float)NP;
    float nf = (float)n;
    float invn = 1.0f / nf;

    double natsum = 0.0;
    for (int i = tid; i < n; i += T2) {
        if (yt[i] == 1) {
            float f = yp[i];
            float c = 1.0f - f;  // MARGIN = 1
            // A = Sum_j sur[i,j],  P = Sum_j sur[i,j]*posf[j]
            float A = fmaf(c, fmaf(nf,  c, 2.0f * s1),  s2);
            float P = fmaf(c, fmaf(npf, c, 2.0f * s1p), s2p);
            float rm  = A * invn;   // row_mean
            float prm = P * invn;   // pos_row_mean
            int j = idx[i];
            float ua = u_all[j];
            float up = u_pos[j];
            float ua_n = fmaf(0.9f, ua, 0.1f * rm);   // (1-GAMMA)*ua + GAMMA*rm
            float up_n = fmaf(0.9f, up, 0.1f * prm);
            // Sum_j p[i,j]*sur[i,j] = (up_n*A - ua_n*P) / ua_n^2
            float contrib = (up_n * A - ua_n * P) / (ua_n * ua_n);
            natsum += (double)contrib;
        }
    }
    natsum = blk_reduce<T2>(natsum, sh, tid);

    if (tid == 0) {
        double nat = (NP > 0.0) ? natsum / (NP * (double)n) : 0.0;
        double result = nat + ADV / (double)n;  // LAMBDA = 1
        out[0] = (float)result;
    }
}

extern "C" void kernel_launch(void* const* d_in, const int* in_sizes, int n_in,
                              void* d_out, int out_size) {
    const float* y_pred     = (const float*)d_in[0];
    const float* y_pred_adv = (const float*)d_in[1];
    const float* u_all      = (const float*)d_in[2];
    const float* u_pos      = (const float*)d_in[3];
    const int*   y_true     = (const int*)d_in[4];
    const int*   index_s    = (const int*)d_in[5];
    float* out = (float*)d_out;
    int n = in_sizes[0];

    k_partials<<<NPART, T1>>>(y_pred, y_pred_adv, y_true, n);
    k_final<<<1, T2>>>(y_pred, u_all, u_pos, y_true, index_s, out, n);
}

// round 6
// speedup vs baseline: 2.0468x; 2.0468x over previous
#include <cuda_runtime.h>

// AdAP_PZ fused single-kernel version.
//
// Math: y_pred in [0,1) => MARGIN - (f_i - f_j) > 0 always, so
//   sur[i,j] = (1 - f_i + f_j)^2 with no clipping; row sums collapse:
//   Sum_j sur[i,j]         = N*c^2     + 2c*S1  + S2      (c = 1 - f_i)
//   Sum_j sur[i,j]*posf[j] = n_pos*c^2 + 2c*S1p + S2p
// => O(N) total work.
//
// Perf: previous 2-kernel version spent 47.6us in a grid=1 finalize kernel
// (sm_103a low-grid issue throttle + 1 SM doing O(N) work). This version is
// ONE kernel, grid=48 (<=1 CTA/SM, co-residency guaranteed), with a
// sense-reversing global barrier between the sum pass and the nat pass.

#define EPSF 1e-12f

constexpr int NB = 48;    // 48 * 256 = 12288 = N
constexpr int TB = 256;

__device__ double g_s1[NB];
__device__ double g_s2[NB];
__device__ double g_s1p[NB];
__device__ double g_s2p[NB];
__device__ double g_np[NB];
__device__ double g_adv[NB];
__device__ double g_nat[NB];

__device__ unsigned g_cnt = 0;
__device__ volatile unsigned g_gen = 0;

__device__ __forceinline__ void grid_barrier() {
    __syncthreads();
    if (threadIdx.x == 0) {
        __threadfence();                      // publish this block's data
        unsigned gen = g_gen;                 // read sense BEFORE arriving
        if (atomicAdd(&g_cnt, 1) == NB - 1) {
            atomicExch(&g_cnt, 0);
            __threadfence();
            g_gen = gen + 1;                  // release
        } else {
            while (g_gen == gen) { __nanosleep(40); }
        }
        __threadfence();                      // acquire
    }
    __syncthreads();
}

// Block-wide double reduction (shuffle tree + 8-warp combine).
__device__ __forceinline__ double bred(double v, double* sh) {
    int tid = threadIdx.x, lane = tid & 31, w = tid >> 5;
#pragma unroll
    for (int o = 16; o; o >>= 1) v += __shfl_down_sync(0xffffffffu, v, o);
    if (lane == 0) sh[w] = v;
    __syncthreads();
    if (w == 0) {
        v = (lane < TB / 32) ? sh[lane] : 0.0;
#pragma unroll
        for (int o = 4; o; o >>= 1) v += __shfl_down_sync(0xffu, v, o);
        if (lane == 0) sh[0] = v;
    }
    __syncthreads();
    double r = sh[0];
    __syncthreads();
    return r;
}

__device__ __forceinline__ float xlogy_f(float x) {
    return (x > 0.0f) ? x * __logf(x) : 0.0f;
}

__global__ void __launch_bounds__(TB) k_fused(const float* __restrict__ yp,
                                              const float* __restrict__ ypa,
                                              const float* __restrict__ u_all,
                                              const float* __restrict__ u_pos,
                                              const int* __restrict__ yt,
                                              const int* __restrict__ idx,
                                              float* __restrict__ out,
                                              int n) {
    __shared__ double sh[TB / 32 > 8 ? TB / 32 : 8];
    const int tid = threadIdx.x;
    const int bid = blockIdx.x;

    // ---- Phase 1: partial sums over this block's slice ----
    double s1 = 0, s2 = 0, s1p = 0, s2p = 0, np = 0, adv = 0;
    for (int i = bid * TB + tid; i < n; i += NB * TB) {
        float f = yp[i];
        float a = ypa[i];
        int pos = (yt[i] == 1);
        double fd = (double)f;
        double ff = fd * fd;
        s1 += fd;
        s2 += ff;
        if (pos) { s1p += fd; s2p += ff; np += 1.0; }
        float t = xlogy_f(f) + xlogy_f(1.0f - f)
                - f * __logf(a + EPSF)
                - (1.0f - f) * __logf(1.0f - a + EPSF);
        adv += (double)t;
    }
    s1  = bred(s1, sh);
    s2  = bred(s2, sh);
    s1p = bred(s1p, sh);
    s2p = bred(s2p, sh);
    np  = bred(np, sh);
    adv = bred(adv, sh);
    if (tid == 0) {
        g_s1[bid] = s1;  g_s2[bid] = s2;
        g_s1p[bid] = s1p; g_s2p[bid] = s2p;
        g_np[bid] = np;  g_adv[bid] = adv;
    }

    grid_barrier();

    // ---- Phase 2: every block redundantly reduces the 48 scalar partials ----
    double S1  = bred((tid < NB) ? g_s1[tid]  : 0.0, sh);
    double S2  = bred((tid < NB) ? g_s2[tid]  : 0.0, sh);
    double S1p = bred((tid < NB) ? g_s1p[tid] : 0.0, sh);
    double S2p = bred((tid < NB) ? g_s2p[tid] : 0.0, sh);
    double NP  = bred((tid < NB) ? g_np[tid]  : 0.0, sh);

    float fs1 = (float)S1, fs2 = (float)S2, fs1p = (float)S1p, fs2p = (float)S2p;
    float npf = (float)NP;
    float nf = (float)n;
    float invn = 1.0f / nf;

    // ---- Phase 3: nat contributions over this block's slice ----
    double natsum = 0.0;
    for (int i = bid * TB + tid; i < n; i += NB * TB) {
        if (yt[i] == 1) {
            float f = yp[i];
            float c = 1.0f - f;  // MARGIN = 1
            float A = fmaf(c, fmaf(nf,  c, 2.0f * fs1),  fs2);   // row sum
            float P = fmaf(c, fmaf(npf, c, 2.0f * fs1p), fs2p);  // pos row sum
            float rm  = A * invn;
            float prm = P * invn;
            int j = idx[i];
            float ua = u_all[j];
            float up = u_pos[j];
            float ua_n = fmaf(0.9f, ua, 0.1f * rm);
            float up_n = fmaf(0.9f, up, 0.1f * prm);
            float contrib = (up_n * A - ua_n * P) / (ua_n * ua_n);
            natsum += (double)contrib;
        }
    }
    natsum = bred(natsum, sh);
    if (tid == 0) g_nat[bid] = natsum;

    grid_barrier();

    // ---- Phase 4: block 0 combines everything ----
    if (bid == 0) {
        double NAT = bred((tid < NB) ? g_nat[tid] : 0.0, sh);
        double ADV = bred((tid < NB) ? g_adv[tid] : 0.0, sh);
        if (tid == 0) {
            double nat = (NP > 0.0) ? NAT / (NP * (double)n) : 0.0;
            out[0] = (float)(nat + ADV / (double)n);  // LAMBDA = 1
        }
    }
}

extern "C" void kernel_launch(void* const* d_in, const int* in_sizes, int n_in,
                              void* d_out, int out_size) {
    const float* y_pred     = (const float*)d_in[0];
    const float* y_pred_adv = (const float*)d_in[1];
    const float* u_all      = (const float*)d_in[2];
    const float* u_pos      = (const float*)d_in[3];
    const int*   y_true     = (const int*)d_in[4];
    const int*   index_s    = (const int*)d_in[5];
    float* out = (float*)d_out;
    int n = in_sizes[0];

    k_fused<<<NB, TB>>>(y_pred, y_pred_adv, u_all, u_pos, y_true, index_s, out, n);
}

// round 8
// speedup vs baseline: 2.9701x; 1.4511x over previous
#include <cuda_runtime.h>

// AdAP_PZ fused single-kernel, barrier-free version.
//
// Math: y_pred in [0,1) => MARGIN - (f_i - f_j) > 0 always, so
//   sur[i,j] = (1 - f_i + f_j)^2 with no clipping; row sums collapse:
//   Sum_j sur[i,j]         = N*c^2     + 2c*S1  + S2      (c = 1 - f_i)
//   Sum_j sur[i,j]*posf[j] = n_pos*c^2 + 2c*S1p + S2p
// => O(N) total work.
//
// Perf: R5's two global spin barriers dominated (23us total, pipes ~0%).
// This version has NO grid barrier: the 5 global scalars (S1,S2,S1p,S2p,NP)
// are cheap enough that EVERY block recomputes them over the full array
// (~1.3us of fma work, 48-way redundant but fully parallel). Each block then
// handles nat+adv for its own 256-element slice; the LAST block to arrive at
// an atomic ticket folds the 48 per-block partials (fixed reduction order =>
// deterministic) and writes the scalar.

#define EPSF 1e-12f

constexpr int NB = 48;   // 48 * 256 = 12288 = N
constexpr int TB = 256;

__device__ double g_adv[NB];
__device__ double g_nat[NB];
__device__ unsigned g_cnt = 0;

__device__ __forceinline__ float xlogy_f(float x) {
    return (x > 0.0f) ? x * __logf(x) : 0.0f;
}

// Interleaved block-wide double reduction of K values; result broadcast to all.
template <int K>
__device__ __forceinline__ void bredK(double* v, double* sh) {
    const int tid = threadIdx.x, lane = tid & 31, w = tid >> 5;
#pragma unroll
    for (int o = 16; o; o >>= 1)
#pragma unroll
        for (int k = 0; k < K; k++) v[k] += __shfl_down_sync(0xffffffffu, v[k], o);
    if (lane == 0)
#pragma unroll
        for (int k = 0; k < K; k++) sh[w * K + k] = v[k];
    __syncthreads();
    if (w == 0) {
#pragma unroll
        for (int k = 0; k < K; k++) v[k] = (lane < TB / 32) ? sh[lane * K + k] : 0.0;
#pragma unroll
        for (int o = 4; o; o >>= 1)
#pragma unroll
            for (int k = 0; k < K; k++) v[k] += __shfl_down_sync(0xffu, v[k], o);
        if (lane == 0)
#pragma unroll
            for (int k = 0; k < K; k++) sh[k] = v[k];
    }
    __syncthreads();
#pragma unroll
    for (int k = 0; k < K; k++) v[k] = sh[k];
    __syncthreads();
}

__global__ void __launch_bounds__(TB) k_fused(const float* __restrict__ yp,
                                              const float* __restrict__ ypa,
                                              const float* __restrict__ u_all,
                                              const float* __restrict__ u_pos,
                                              const int* __restrict__ yt,
                                              const int* __restrict__ idx,
                                              float* __restrict__ out,
                                              int n) {
    __shared__ double sh[(TB / 32) * 5];
    __shared__ int s_last;
    const int tid = threadIdx.x;
    const int bid = blockIdx.x;

    // ---- Pass A (every block, full array): S1, S2, S1p, S2p, NP ----
    float s1 = 0.f, s2 = 0.f, s1p = 0.f, s2p = 0.f, npc = 0.f;
    if ((n & 3) == 0) {
        const float4* yp4 = (const float4*)yp;
        const int4*   yt4 = (const int4*)yt;
        const int n4 = n >> 2;
        for (int i = tid; i < n4; i += TB) {
            float4 f4 = yp4[i];
            int4   t4 = yt4[i];
            {
                float f = f4.x; float pf = (t4.x == 1) ? 1.f : 0.f;
                s1 += f; s2 = fmaf(f, f, s2);
                float t = pf * f; s1p += t; s2p = fmaf(t, f, s2p); npc += pf;
            }
            {
                float f = f4.y; float pf = (t4.y == 1) ? 1.f : 0.f;
                s1 += f; s2 = fmaf(f, f, s2);
                float t = pf * f; s1p += t; s2p = fmaf(t, f, s2p); npc += pf;
            }
            {
                float f = f4.z; float pf = (t4.z == 1) ? 1.f : 0.f;
                s1 += f; s2 = fmaf(f, f, s2);
                float t = pf * f; s1p += t; s2p = fmaf(t, f, s2p); npc += pf;
            }
            {
                float f = f4.w; float pf = (t4.w == 1) ? 1.f : 0.f;
                s1 += f; s2 = fmaf(f, f, s2);
                float t = pf * f; s1p += t; s2p = fmaf(t, f, s2p); npc += pf;
            }
        }
    } else {
        for (int i = tid; i < n; i += TB) {
            float f = yp[i]; float pf = (yt[i] == 1) ? 1.f : 0.f;
            s1 += f; s2 = fmaf(f, f, s2);
            float t = pf * f; s1p += t; s2p = fmaf(t, f, s2p); npc += pf;
        }
    }
    double v[5] = {(double)s1, (double)s2, (double)s1p, (double)s2p, (double)npc};
    bredK<5>(v, sh);
    const double S1 = v[0], S2 = v[1], S1p = v[2], S2p = v[3], NP = v[4];

    const float fs1 = (float)S1, fs2 = (float)S2;
    const float fs1p = (float)S1p, fs2p = (float)S2p;
    const float npf = (float)NP;
    const float nf = (float)n;
    const float invn = 1.0f / nf;

    // ---- Pass B (this block's slice): adv KL term + nat contribution ----
    double adv = 0.0, natsum = 0.0;
    for (int i = bid * TB + tid; i < n; i += NB * TB) {
        float f = yp[i];
        float a = ypa[i];
        float t = xlogy_f(f) + xlogy_f(1.0f - f)
                - f * __logf(a + EPSF)
                - (1.0f - f) * __logf(1.0f - a + EPSF);
        adv += (double)t;
        if (yt[i] == 1) {
            float c = 1.0f - f;  // MARGIN = 1
            float A = fmaf(c, fmaf(nf,  c, 2.0f * fs1),  fs2);   // row sum
            float P = fmaf(c, fmaf(npf, c, 2.0f * fs1p), fs2p);  // pos row sum
            float rm  = A * invn;
            float prm = P * invn;
            int j = idx[i];
            float ua_n = fmaf(0.9f, u_all[j], 0.1f * rm);
            float up_n = fmaf(0.9f, u_pos[j], 0.1f * prm);
            natsum += (double)((up_n * A - ua_n * P) / (ua_n * ua_n));
        }
    }
    double w2[2] = {adv, natsum};
    bredK<2>(w2, sh);

    // ---- Ticket: last block to arrive does the final fold ----
    if (tid == 0) {
        g_adv[bid] = w2[0];
        g_nat[bid] = w2[1];
        __threadfence();
        int last = (atomicAdd(&g_cnt, 1) == NB - 1);
        if (last) atomicExch(&g_cnt, 0);   // reset for next graph replay
        s_last = last;
    }
    __syncthreads();

    if (s_last && tid < 32) {
        __threadfence();  // acquire: see all blocks' g_adv/g_nat
        double a = 0.0, nt = 0.0;
        for (int k = tid; k < NB; k += 32) { a += g_adv[k]; nt += g_nat[k]; }
#pragma unroll
        for (int o = 16; o; o >>= 1) {
            a  += __shfl_down_sync(0xffffffffu, a, o);
            nt += __shfl_down_sync(0xffffffffu, nt, o);
        }
        if (tid == 0) {
            double nat = (NP > 0.0) ? nt / (NP * (double)n) : 0.0;
            out[0] = (float)(nat + a / (double)n);  // LAMBDA = 1
        }
    }
}

extern "C" void kernel_launch(void* const* d_in, const int* in_sizes, int n_in,
                              void* d_out, int out_size) {
    const float* y_pred     = (const float*)d_in[0];
    const float* y_pred_adv = (const float*)d_in[1];
    const float* u_all      = (const float*)d_in[2];
    const float* u_pos      = (const float*)d_in[3];
    const int*   y_true     = (const int*)d_in[4];
    const int*   index_s    = (const int*)d_in[5];
    float* out = (float*)d_out;
    int n = in_sizes[0];

    k_fused<<<NB, TB>>>(y_pred, y_pred_adv, u_all, u_pos, y_true, index_s, out, n);
}